// round 3
// baseline (speedup 1.0000x reference)
#include <cuda_runtime.h>
#include <math.h>

#define B_   128
#define N_   8
#define LQ   32
#define LD   256
#define D_   128
#define NEGV (-9999.0f)
#define SMEM_BYTES 50944

__device__ float g_scores[2 * N_ * B_];   // [z][n][b]

// ---- packed f32x2 helpers (FFMA2 — only reachable via explicit PTX) ----
__device__ __forceinline__ void ffma2(unsigned long long& c, unsigned long long a,
                                      unsigned long long b) {
    asm("fma.rn.f32x2 %0, %1, %2, %0;" : "+l"(c) : "l"(a), "l"(b));
}
__device__ __forceinline__ void fadd2(unsigned long long& c, unsigned long long a) {
    asm("add.rn.f32x2 %0, %0, %1;" : "+l"(c) : "l"(a));
}
__device__ __forceinline__ float hsum2(unsigned long long c) {
    return __uint_as_float((unsigned)c) + __uint_as_float((unsigned)(c >> 32));
}

// ---------------------------------------------------------------------------
// MaxSim: grid (B, N, 2), 256 threads, 2 CTAs/SM.
// Per CTA: compact active rows; chunks of 64 rows; row-major swizzled tiles;
// 4q x 4r thread tile with k-paired FFMA2; 2-way K-split across warp halves.
// Scores = (q.d) * inv||d|| * inv||q||  (norms folded post-GEMM).
// ---------------------------------------------------------------------------
__global__ void __launch_bounds__(256, 2)
maxsim_kernel(const float* __restrict__ q, const float* __restrict__ dcq,
              const float* __restrict__ dorig, const int* __restrict__ mask)
{
    extern __shared__ float4 smem4[];
    float4* sD4  = smem4;                 // 64 rows x 32 quads  (32 KB)
    float4* sQ4  = smem4 + 2048;          // 32 rows x 32 quads  (16 KB)
    float*  tail = (float*)(smem4 + 3072);
    float*  sInvD = tail;                 // 64
    float*  sInvQ = tail + 64;            // 32
    float*  sP    = tail + 96;            // 64
    int*    sAct  = (int*)(tail + 160);   // 256
    int*    sCnt  = (int*)(tail + 416);
    unsigned long long* sRed = (unsigned long long*)sD4;  // overlay (16 KB)

    const int b = blockIdx.x, n = blockIdx.y, z = blockIdx.z;
    const int t = threadIdx.x;
    const int lane = t & 31, w = t >> 5;
    const float* __restrict__ dpair = (z ? dorig : dcq) + (size_t)(n * B_ + b) * (LD * D_);

    if (t == 0) *sCnt = 0;
    __syncthreads();

    // ---- q tile: raw load + swizzled store + per-row inverse norm ----
    {
        const float4* qsrc = (const float4*)(q + (size_t)b * LQ * D_);
#pragma unroll
        for (int it = 0; it < 4; it++) {
            int li = it * 256 + t;
            int row = li >> 5;                       // = it*8 + w
            float4 v = qsrc[li];
            sQ4[row * 32 + (lane ^ ((row >> 2) & 7))] = v;
            float ss = v.x * v.x + v.y * v.y + v.z * v.z + v.w * v.w;
#pragma unroll
            for (int o = 16; o; o >>= 1) ss += __shfl_xor_sync(~0u, ss, o);
            if (lane == 0) sInvQ[row] = 1.0f / fmaxf(sqrtf(ss), 1e-12f);
        }
    }

    // ---- mask compaction (order irrelevant: max is commutative) ----
    if (mask[(n * B_ + b) * LD + t]) sAct[atomicAdd(sCnt, 1)] = t;
    __syncthreads();
    const int cnt = *sCnt;
    if (cnt == 0) {                         // all masked: scores = 32 * NEG
        if (t == 0) g_scores[(z * N_ + n) * B_ + b] = 32.0f * NEGV;
        return;
    }
    const int nch = (cnt + 63) >> 6;

    // ---- thread geometry ----
    const int ks  = w >> 2;            // K-slice: quads [16ks, 16ks+16)
    const int wr  = (w >> 1) & 1;      // row block (32 rows)
    const int wq  = w & 1;             // query block (16 queries)
    const int rgl = lane >> 2;         // 8 row groups
    const int qgl = lane & 3;          // 4 query groups
    const int row0 = 32 * wr + 4 * rgl;
    const int q0   = 16 * wq + 4 * qgl;
    const int qxor = (4 * wq + qgl) & 7;   // == (j>>2)&7 for this thread's queries
    const int kq0  = ks * 16;

    unsigned long long acc[16];
#pragma unroll
    for (int i = 0; i < 16; i++) acc[i] = 0ull;
    float mx[4] = {-1e30f, -1e30f, -1e30f, -1e30f};

    // ---- prefetch chunk 0 (tail padded by duplicating a valid row) ----
    float4 pv[8];
#pragma unroll
    for (int it = 0; it < 8; it++) {
        int li = it * 256 + t;
        int row = li >> 5, kq = li & 31;
        int idx = row; if (idx >= cnt) idx = cnt - 1;
        pv[it] = *(const float4*)(dpair + sAct[idx] * D_ + kq * 4);
    }

    for (int ch = 0; ch < nch; ch++) {
        __syncthreads();
        // ---- store tile (swizzled) + per-row inverse norm ----
#pragma unroll
        for (int it = 0; it < 8; it++) {
            int row = it * 8 + w;                    // kq == lane
            float4 v = pv[it];
            sD4[row * 32 + (lane ^ ((row >> 2) & 7))] = v;
            float ss = v.x * v.x + v.y * v.y + v.z * v.z + v.w * v.w;
#pragma unroll
            for (int o = 16; o; o >>= 1) ss += __shfl_xor_sync(~0u, ss, o);
            if (lane == 0) sInvD[row] = 1.0f / fmaxf(sqrtf(ss), 1e-12f);
        }
        __syncthreads();

        // ---- prefetch next chunk (hidden behind GEMM) ----
        if (ch + 1 < nch) {
#pragma unroll
            for (int it = 0; it < 8; it++) {
                int li = it * 256 + t;
                int row = li >> 5, kq = li & 31;
                int idx = (ch + 1) * 64 + row; if (idx >= cnt) idx = cnt - 1;
                pv[it] = *(const float4*)(dpair + sAct[idx] * D_ + kq * 4);
            }
        }

        // ---- GEMM: 16 quads (64 k) of this thread's K-slice ----
#pragma unroll 4
        for (int kk = 0; kk < 16; kk++) {
            int kq = kq0 + kk;
            ulonglong2 qv[4], dv[4];
#pragma unroll
            for (int i = 0; i < 4; i++)
                qv[i] = *(const ulonglong2*)(sQ4 + (q0 + i) * 32 + (kq ^ qxor));
#pragma unroll
            for (int i = 0; i < 4; i++)
                dv[i] = *(const ulonglong2*)(sD4 + (row0 + i) * 32 + (kq ^ rgl));
#pragma unroll
            for (int qi = 0; qi < 4; qi++)
#pragma unroll
                for (int ri = 0; ri < 4; ri++) {
                    ffma2(acc[qi * 4 + ri], dv[ri].x, qv[qi].x);
                    ffma2(acc[qi * 4 + ri], dv[ri].y, qv[qi].y);
                }
        }
        __syncthreads();

        // ---- cross-K-slice combine (overlay on dead tile) + epilogue ----
        if (ks == 1) {
#pragma unroll
            for (int i = 0; i < 16; i++) sRed[(t - 128) * 16 + i] = acc[i];
        }
        __syncthreads();
        if (ks == 0) {
#pragma unroll
            for (int qi = 0; qi < 4; qi++)
#pragma unroll
                for (int ri = 0; ri < 4; ri++) {
                    fadd2(acc[qi * 4 + ri], sRed[t * 16 + qi * 4 + ri]);
                    float val = hsum2(acc[qi * 4 + ri]) * sInvD[row0 + ri];
                    mx[qi] = fmaxf(mx[qi], val);
                }
        }
#pragma unroll
        for (int i = 0; i < 16; i++) acc[i] = 0ull;
    }

    // ---- reduce max over row groups, then sum over queries ----
    if (ks == 0) {
#pragma unroll
        for (int qi = 0; qi < 4; qi++) {
#pragma unroll
            for (int o = 16; o >= 4; o >>= 1)
                mx[qi] = fmaxf(mx[qi], __shfl_down_sync(~0u, mx[qi], o));
        }
        if (lane < 4) {
#pragma unroll
            for (int qi = 0; qi < 4; qi++) sP[w * 16 + lane * 4 + qi] = mx[qi];
        }
    }
    __syncthreads();
    if (t < 32) {
        int wq2 = t >> 4, qg2 = (t >> 2) & 3, qq2 = t & 3;
        float v = fmaxf(sP[(0 * 2 + wq2) * 16 + qg2 * 4 + qq2],
                        sP[(1 * 2 + wq2) * 16 + qg2 * 4 + qq2]) * sInvQ[t];
#pragma unroll
        for (int o = 16; o; o >>= 1) v += __shfl_xor_sync(~0u, v, o);
        if (t == 0) g_scores[(z * N_ + n) * B_ + b] = v;
    }
}

// ---------------------------------------------------------------------------
// KL(batchmean) over [B, N]
// ---------------------------------------------------------------------------
__global__ void __launch_bounds__(128) loss_kernel(float* __restrict__ out)
{
    int b = threadIdx.x;
    float s[N_], tt[N_];
#pragma unroll
    for (int n = 0; n < N_; n++) {
        s[n]  = g_scores[n * B_ + b];
        tt[n] = g_scores[(N_ + n) * B_ + b];
    }
    float ms = s[0], mt = tt[0];
#pragma unroll
    for (int n = 1; n < N_; n++) { ms = fmaxf(ms, s[n]); mt = fmaxf(mt, tt[n]); }
    float es = 0.f, et = 0.f;
#pragma unroll
    for (int n = 0; n < N_; n++) { es += expf(s[n] - ms); et += expf(tt[n] - mt); }
    float lses = ms + logf(es);
    float lset = mt + logf(et);
    float kl = 0.f;
#pragma unroll
    for (int n = 0; n < N_; n++) {
        float lt = tt[n] - lset;
        float ls = s[n]  - lses;
        kl += expf(lt) * (lt - ls);
    }
    __shared__ float red[128];
    red[b] = kl;
    __syncthreads();
#pragma unroll
    for (int o = 64; o; o >>= 1) {
        if (b < o) red[b] += red[b + o];
        __syncthreads();
    }
    if (b == 0) out[0] = red[0] / (float)B_;
}

// ---------------------------------------------------------------------------
extern "C" void kernel_launch(void* const* d_in, const int* in_sizes, int n_in,
                              void* d_out, int out_size)
{
    const float* q     = (const float*)d_in[0];   // [B,Lq,D]
    const float* dcq   = (const float*)d_in[1];   // [N,B,Ld,D]
    const float* dorig = (const float*)d_in[2];   // [N,B,Ld,D]
    const int*   mask  = (const int*)d_in[3];     // [N,B,Ld]

    cudaFuncSetAttribute(maxsim_kernel,
                         cudaFuncAttributeMaxDynamicSharedMemorySize, SMEM_BYTES);
    dim3 grid(B_, N_, 2);
    maxsim_kernel<<<grid, 256, SMEM_BYTES>>>(q, dcq, dorig, mask);
    loss_kernel<<<1, 128>>>((float*)d_out);
}